// round 10
// baseline (speedup 1.0000x reference)
#include <cuda_runtime.h>
#include <math.h>

#define NP 8732
#define NG 16
#define NC 21
#define SPLIT 3
#define STILES 91          // 273 = 3 * 91
#define TPB 512
#define WPB 16
#define MAXB 128

__device__ unsigned long long g_best[MAXB * NG];
__device__ float g_sll[MAXB * SPLIT];
__device__ float g_slc[MAXB * SPLIT];
__device__ int   g_snp[MAXB * SPLIT];
__device__ float g_lcb[MAXB * NP];
__device__ unsigned char g_gpb[MAXB * NP];
__device__ float g_bll[MAXB];
__device__ float g_blc[MAXB];
__device__ int   g_bnp[MAXB];
__device__ unsigned g_barr[MAXB];
__device__ unsigned g_arrive = 0;

// smooth-L1 loc loss; single implementation for bit-identical math everywhere
__device__ __forceinline__ float sl1_calc(const float* __restrict__ ld,
                                          float4 pr, const float* t) {
    float vx = 0.1f * pr.z;
    float vy = 0.1f * pr.w;
    float lts[10];
    lts[0] = ((t[0] + t[2]) * 0.5f - pr.x) / vx;
    lts[1] = ((t[1] + t[3]) * 0.5f - pr.y) / vy;
    lts[2] = logf((t[2] - t[0]) / pr.z) / 0.2f;
    lts[3] = logf((t[3] - t[1]) / pr.w) / 0.2f;
    lts[4] = logf(t[4] / pr.z + 0.1f) / 0.2f;
    lts[5] = logf(t[5] / pr.w + 0.1f) / 0.2f;
    lts[6] = logf(t[6] / pr.z + 0.1f) / 0.2f;
    lts[7] = logf(t[7] / pr.w + 0.1f) / 0.2f;
    lts[8] = (t[8] - pr.x) / vx;
    lts[9] = (t[9] - pr.y) / vy;
    float ll = 0.0f;
#pragma unroll
    for (int j = 0; j < 10; j++) {
        float d  = __ldg(ld + j) - lts[j];
        float ad = fabsf(d);
        ll += (ad < 1.0f) ? (0.5f * d) * d : (ad - 0.5f);
    }
    return ll;
}

struct __align__(16) SmemA {
    float stage[WPB * 672];
    unsigned hist[2048];
    float tg[NG * 11];
    float4 box[NG];
    float taa[NG];
    unsigned long long sbest[NG];
    unsigned char sgp[STILES * 32 + 4];
    int   bp[NG];
    float dll[NG];
    float dlc[NG];
    int   dnp[NG];
    float rf[WPB];
    float rf2[WPB];
    int   ri[WPB];
    unsigned gsum[WPB];
    int   bc[4];
    int   flag;
};

__global__ void __launch_bounds__(TPB, 3) mb_pass(
    const float* __restrict__ loc_data,   // [B, NP, 10]
    const float* __restrict__ conf_data,  // [B, NP, 21]
    const float* __restrict__ priors,     // [NP, 4]
    const float* __restrict__ targets,    // [B, NG, 11]
    float* __restrict__ out, int B)
{
    extern __shared__ char smem_raw[];
    SmemA* S = (SmemA*)smem_raw;
    unsigned* hist = S->hist;

    const int b    = blockIdx.x / SPLIT;
    const int sl   = blockIdx.x % SPLIT;
    const int tid  = threadIdx.x;
    const int lane = tid & 31;
    const int wrp  = tid >> 5;
    const int T0   = sl * STILES;
    const int P0   = T0 * 32;
    const int P1   = (NP < P0 + STILES * 32) ? NP : (P0 + STILES * 32);
    float* glc = g_lcb + (size_t)b * NP;

    for (int i = tid; i < NG * 11; i += TPB)
        S->tg[i] = targets[b * NG * 11 + i];
    if (tid < NG) S->sbest[tid] = 0ull;
    __syncthreads();
    if (tid < NG) {
        const float* t = S->tg + tid * 11;
        float4 bx = make_float4(t[0], t[1], t[2], t[3]);
        S->box[tid] = bx;
        S->taa[tid] = (bx.z - bx.x) * (bx.w - bx.y);
    }
    __syncthreads();

    // ---- pass 1: matching over this slice (fast-quotient decisions) ----
#pragma unroll 1
    for (int p = P0 + tid; p < P1; p += TPB) {
        float4 pr = __ldg((const float4*)priors + p);
        float pax = pr.x - 0.5f * pr.z;
        float pay = pr.y - 0.5f * pr.w;
        float pbx = pr.x + 0.5f * pr.z;
        float pby = pr.y + 0.5f * pr.w;
        float pare = (pbx - pax) * (pby - pay);
        float bq = -1.0f;
        int bg = 0;
#pragma unroll
        for (int g = 0; g < NG; g++) {
            float4 t = S->box[g];
            float ix = fminf(t.z, pbx) - fmaxf(t.x, pax);
            float iy = fminf(t.w, pby) - fmaxf(t.y, pay);
            ix = fmaxf(ix, 0.0f);
            iy = fmaxf(iy, 0.0f);
            float inter = ix * iy;
            float den = (S->taa[g] + pare) - inter;   // > 0
            float q = __fdividef(inter, den);
            if (q > bq) { bq = q; bg = g; }           // strict > : first max over g
            unsigned long long pk =
                ((unsigned long long)__float_as_uint(q) << 32) |
                (unsigned)(0x7fffffff - p);
            unsigned long long cur = *(volatile unsigned long long*)&S->sbest[g];
            if (pk > cur) atomicMax(&S->sbest[g], pk);
        }
        unsigned char v = (unsigned char)bg | ((bq >= 0.5f) ? 0x10 : 0x00);
        S->sgp[p - P0] = v;
        g_gpb[(size_t)b * NP + p] = v;
    }
    __syncthreads();
    if (tid < NG) atomicMax(&g_best[b * NG + tid], S->sbest[tid]);

    // ---- pass 2: per-prior losses over this slice ----
    float ll = 0.0f, lcp = 0.0f;
    int   np = 0;
    float* stg = S->stage + wrp * 672;
    float4* stg4 = (float4*)stg;
    const float* confb = conf_data + (size_t)b * NP * NC;

#pragma unroll 1
    for (int tile = T0 + wrp; tile < T0 + STILES; tile += WPB) {
        const int p0 = tile * 32;
        const int cnt = (NP - p0 < 32) ? (NP - p0) : 32;
        const int tcnt4 = (cnt * NC) >> 2;
        const float4* cb4 = (const float4*)(confb + (size_t)p0 * NC);
#pragma unroll
        for (int j = 0; j < 6; j++) {
            int idx2 = j * 32 + lane;
            if (idx2 < tcnt4) stg4[idx2] = __ldg(cb4 + idx2);
        }
        __syncwarp();

        const int p = p0 + lane;
        if (p < NP) {
            unsigned gpv = S->sgp[p - P0];
            int gi = gpv & 15;
            bool pos = (gpv & 0x10) != 0;
            int conf = pos ? ((int)S->tg[gi * 11 + 10] + 1) : 0;

            const float* row = stg + lane * NC;
            float s = 0.0f;
#pragma unroll
            for (int j = 0; j < NC; j++) s += __expf(row[j]);
            float lca = __logf(s) - row[conf];

            float lc = lca;
            if (pos) {
                lc = 0.0f;
                np++;
                lcp += lca;
                float4 pr = __ldg((const float4*)priors + p);
                ll += sl1_calc(loc_data + ((size_t)b * NP + p) * 10, pr,
                               S->tg + gi * 11);
            }
            glc[p] = lc;
        }
        __syncwarp();
    }

    // ---- block reduce -> per-slice partials ----
#pragma unroll
    for (int o = 16; o > 0; o >>= 1) {
        ll  += __shfl_down_sync(0xffffffffu, ll, o);
        lcp += __shfl_down_sync(0xffffffffu, lcp, o);
        np  += __shfl_down_sync(0xffffffffu, np, o);
    }
    if (lane == 0) { S->rf[wrp] = ll; S->rf2[wrp] = lcp; S->ri[wrp] = np; }
    __syncthreads();
    if (tid < 32) {
        float ll_t = (tid < WPB) ? S->rf[tid] : 0.0f;
        float lcp_t = (tid < WPB) ? S->rf2[tid] : 0.0f;
        int   np_t = (tid < WPB) ? S->ri[tid] : 0;
#pragma unroll
        for (int o = 8; o > 0; o >>= 1) {
            ll_t  += __shfl_down_sync(0xffffffffu, ll_t, o);
            lcp_t += __shfl_down_sync(0xffffffffu, lcp_t, o);
            np_t  += __shfl_down_sync(0xffffffffu, np_t, o);
        }
        if (tid == 0) {
            g_sll[blockIdx.x] = ll_t;
            g_slc[blockIdx.x] = lcp_t;
            g_snp[blockIdx.x] = np_t;
            __threadfence();
            unsigned t = atomicAdd(&g_barr[b], 1u);
            S->flag = (t == SPLIT - 1);
        }
    }
    __syncthreads();
    if (!S->flag) return;        // non-last CTAs of this batch exit

    // ================= per-batch finalize (last CTA of batch) =================
    if (tid < NG) {
        S->bp[tid] = 0x7fffffff - (int)(unsigned)(g_best[b * NG + tid] & 0xffffffffull);
        g_best[b * NG + tid] = 0ull;      // reset for next graph replay
    }
    if (tid == 0) g_barr[b] = 0u;         // reset for next graph replay
    __syncthreads();

    // corrections for overridden priors (<=16), exact semantics
    if (tid < NG) {
        const int j = tid;
        const int p = S->bp[j];
        bool last = true;
#pragma unroll
        for (int j2 = j + 1; j2 < NG; j2++)
            if (S->bp[j2] == p) last = false;
        float dll = 0.0f, dlc = 0.0f;
        int dnp = 0;
        if (last) {
            unsigned old = g_gpb[(size_t)b * NP + p];
            int gio = old & 15;
            bool poso = (old & 0x10) != 0;
            if (!(poso && gio == j)) {
                const float* c = conf_data + ((size_t)b * NP + p) * NC;
                float s = 0.0f;
#pragma unroll
                for (int j2 = 0; j2 < NC; j2++) s += __expf(__ldg(c + j2));
                float lse = __logf(s);
                const float* tn = S->tg + j * 11;
                int cn = (int)tn[10] + 1;
                float4 pr2 = __ldg((const float4*)priors + p);
                const float* ld = loc_data + ((size_t)b * NP + p) * 10;
                dlc = lse - __ldg(c + cn);
                dll = sl1_calc(ld, pr2, tn);
                dnp = poso ? 0 : 1;
                if (poso) {
                    const float* to = S->tg + gio * 11;
                    int co = (int)to[10] + 1;
                    dlc -= (lse - __ldg(c + co));
                    dll -= sl1_calc(ld, pr2, to);
                }
            }
            glc[p] = 0.0f;
        }
        S->dll[j] = dll;
        S->dlc[j] = dlc;
        S->dnp[j] = dnp;
    }
    __syncthreads();
    if (tid == 0) {
        float ll_t = 0.0f, lcp_t = 0.0f;
        int   np_t = 0;
#pragma unroll
        for (int s2 = 0; s2 < SPLIT; s2++) {
            ll_t  += g_sll[b * SPLIT + s2];
            lcp_t += g_slc[b * SPLIT + s2];
            np_t  += g_snp[b * SPLIT + s2];
        }
#pragma unroll
        for (int j = 0; j < NG; j++) {
            ll_t  += S->dll[j];
            lcp_t += S->dlc[j];
            np_t  += S->dnp[j];
        }
        S->rf[0] = ll_t; S->rf2[0] = lcp_t; S->bc[0] = np_t;
    }
    __syncthreads();
    const int np_tot = S->bc[0];
    const float ll_tot = S->rf[0];
    const float lcp_tot = S->rf2[0];
    int k = 3 * np_tot;
    if (k > NP - 1) k = NP - 1;

    // exact top-k sum via 3-round radix select over glc (L2-hot)
    float Ssum = 0.0f;
    if (k > 0) {
        unsigned prefix = 0u, pmask = 0u;
        const int shifts[3] = {21, 10, 0};
        const int rbits[3]  = {11, 11, 10};
        int kk = k;
        for (int r = 0; r < 3; r++) {
            for (int i = tid; i < 2048; i += TPB) hist[i] = 0u;
            __syncthreads();
            const unsigned nb = 1u << rbits[r];
#pragma unroll 1
            for (int p = tid; p < 9216; p += TPB) {
                bool valid = p < NP;
                unsigned bb = valid ? __float_as_uint(glc[p]) : 0u;
                bool sel = valid && ((bb & pmask) == prefix);
                unsigned bin = sel ? ((bb >> shifts[r]) & (nb - 1u)) : 0xffffffffu;
                unsigned grp = __match_any_sync(0xffffffffu, bin);
                if (sel && lane == (__ffs(grp) - 1))
                    atomicAdd(&hist[bin], (unsigned)__popc(grp));
            }
            __syncthreads();
            unsigned c0 = hist[tid * 4 + 0], c1 = hist[tid * 4 + 1];
            unsigned c2 = hist[tid * 4 + 2], c3 = hist[tid * 4 + 3];
            unsigned sloc = c0 + c1 + c2 + c3;
            unsigned suf = sloc;
#pragma unroll
            for (int o = 1; o < 32; o <<= 1) {
                unsigned v = __shfl_down_sync(0xffffffffu, suf, o);
                if (lane + o < 32) suf += v;
            }
            if (lane == 0) S->gsum[wrp] = suf;
            __syncthreads();
            unsigned above = 0;
            for (int w = wrp + 1; w < WPB; w++) above += S->gsum[w];
            unsigned excl3 = above + (suf - sloc);
            unsigned excl2 = excl3 + c3;
            unsigned excl1 = excl2 + c2;
            unsigned excl0 = excl1 + c1;
            unsigned ukk = (unsigned)kk;
            if (excl3 < ukk && ukk <= excl3 + c3) { S->bc[1] = tid * 4 + 3; S->bc[2] = (int)(ukk - excl3); }
            if (excl2 < ukk && ukk <= excl2 + c2) { S->bc[1] = tid * 4 + 2; S->bc[2] = (int)(ukk - excl2); }
            if (excl1 < ukk && ukk <= excl1 + c1) { S->bc[1] = tid * 4 + 1; S->bc[2] = (int)(ukk - excl1); }
            if (excl0 < ukk && ukk <= excl0 + c0) { S->bc[1] = tid * 4 + 0; S->bc[2] = (int)(ukk - excl0); }
            __syncthreads();
            int chosen = S->bc[1];
            kk = S->bc[2];
            prefix |= ((unsigned)chosen) << shifts[r];
            pmask  |= ((1u << rbits[r]) - 1u) << shifts[r];
            __syncthreads();
        }
        const float tv = __uint_as_float(prefix);
        float sgt = 0.0f;
        int   cgt = 0;
#pragma unroll 1
        for (int p = tid; p < NP; p += TPB) {
            float v = glc[p];
            if (__float_as_uint(v) > prefix) { sgt += v; cgt++; }
        }
#pragma unroll
        for (int o = 16; o > 0; o >>= 1) {
            sgt += __shfl_down_sync(0xffffffffu, sgt, o);
            cgt += __shfl_down_sync(0xffffffffu, cgt, o);
        }
        if (lane == 0) { S->rf[wrp] = sgt; S->ri[wrp] = cgt; }
        __syncthreads();
        if (tid == 0) {
            float sgt_t = 0.0f;
            int   cgt_t = 0;
            for (int w = 0; w < WPB; w++) { sgt_t += S->rf[w]; cgt_t += S->ri[w]; }
            Ssum = sgt_t + (float)(k - cgt_t) * tv;
        }
    }

    // publish per-batch; globally-last batch CTA writes the output
    __shared__ bool slast;
    if (tid == 0) {
        g_bll[b] = ll_tot;
        g_blc[b] = lcp_tot + Ssum;
        g_bnp[b] = np_tot;
        __threadfence();
        unsigned t = atomicAdd(&g_arrive, 1u);
        slast = (t == (unsigned)(B - 1));
        if (slast) g_arrive = 0u;
    }
    __syncthreads();
    if (slast) {
        float fll = 0.0f, flc = 0.0f;
        int   fnp = 0;
        for (int i = tid; i < B; i += TPB) {
            fll += g_bll[i]; flc += g_blc[i]; fnp += g_bnp[i];
        }
#pragma unroll
        for (int o = 16; o > 0; o >>= 1) {
            fll += __shfl_down_sync(0xffffffffu, fll, o);
            flc += __shfl_down_sync(0xffffffffu, flc, o);
            fnp += __shfl_down_sync(0xffffffffu, fnp, o);
        }
        if (lane == 0) { S->rf[wrp] = fll; S->rf2[wrp] = flc; S->ri[wrp] = fnp; }
        __syncthreads();
        if (tid == 0) {
            float tll = 0.0f, tlc = 0.0f;
            int tnp = 0;
            for (int w = 0; w < WPB; w++) { tll += S->rf[w]; tlc += S->rf2[w]; tnp += S->ri[w]; }
            float N = (float)tnp;
            out[0] = tll / N;
            out[1] = tlc / N;
        }
    }
}

extern "C" void kernel_launch(void* const* d_in, const int* in_sizes, int n_in,
                              void* d_out, int out_size) {
    const float* loc     = (const float*)d_in[0];
    const float* conf    = (const float*)d_in[1];
    const float* priors  = (const float*)d_in[2];
    const float* targets = (const float*)d_in[3];
    const int B = in_sizes[0] / (NP * 10);

    cudaFuncSetAttribute(mb_pass, cudaFuncAttributeMaxDynamicSharedMemorySize,
                         (int)sizeof(SmemA));
    mb_pass<<<B * SPLIT, TPB, sizeof(SmemA)>>>(loc, conf, priors, targets,
                                               (float*)d_out, B);
}

// round 12
// speedup vs baseline: 1.2955x; 1.2955x over previous
#include <cuda_runtime.h>
#include <math.h>

#define NP 8732
#define NG 16
#define NC 21
#define NTHREADS 1024
#define NWARPS 32
#define NTILES 273

__device__ float g_bll[256];
__device__ float g_blc[256];
__device__ int   g_bnp[256];
__device__ unsigned g_arrive = 0;

struct __align__(16) Smem {
    float  stage[NWARPS * 672];    // conf staging; aliased as radix hist later
    float  lc[NP];
    float  tg[NG * 11];
    float4 box[NG];
    float  taa[NG];
    unsigned char gp[NP + 4];      // gi | (pos<<4)
    float  qmaxw[NG * NWARPS];     // per-warp per-gt maxima
    float  qmax[NG];
    int    bp[NG];
    float  rf[NWARPS];
    float  rf2[NWARPS];
    int    ri[NWARPS];
    unsigned gsum[NWARPS];
    int    bc[4];
};

// Rounding-pinned prior box derivation: every op is an explicit _rn intrinsic,
// so codegen is bit-identical at every call site (no contraction freedom).
__device__ __forceinline__ void prior_derive(float4 pr, float& pax, float& pay,
                                             float& pbx, float& pby, float& pare) {
    pax = __fmaf_rn(-0.5f, pr.z, pr.x);
    pay = __fmaf_rn(-0.5f, pr.w, pr.y);
    pbx = __fmaf_rn(0.5f, pr.z, pr.x);
    pby = __fmaf_rn(0.5f, pr.w, pr.y);
    pare = __fmul_rn(__fsub_rn(pbx, pax), __fsub_rn(pby, pay));
}

// Rounding-pinned IoU quotient — deterministic bits at every call site.
__device__ __forceinline__ float qcalc(float4 t, float taa, float pax, float pay,
                                       float pbx, float pby, float pare) {
    float ix = __fsub_rn(fminf(t.z, pbx), fmaxf(t.x, pax));
    float iy = __fsub_rn(fminf(t.w, pby), fmaxf(t.y, pay));
    ix = fmaxf(ix, 0.0f);
    iy = fmaxf(iy, 0.0f);
    float inter = __fmul_rn(ix, iy);
    float den = __fsub_rn(__fadd_rn(taa, pare), inter);   // > 0
    return __fdividef(inter, den);
}

__global__ void __launch_bounds__(NTHREADS, 1) mb_main(
    const float* __restrict__ loc_data,   // [B, NP, 10]
    const float* __restrict__ conf_data,  // [B, NP, 21]
    const float* __restrict__ priors,     // [NP, 4]
    const float* __restrict__ targets,    // [B, NG, 11]
    float* __restrict__ out)
{
    extern __shared__ char smem_raw[];
    Smem* S = (Smem*)smem_raw;
    unsigned* hist = (unsigned*)S->stage;

    const int b    = blockIdx.x;
    const int tid  = threadIdx.x;
    const int lane = tid & 31;
    const int wrp  = tid >> 5;

    for (int i = tid; i < NG * 11; i += NTHREADS)
        S->tg[i] = targets[b * NG * 11 + i];
    __syncthreads();
    if (tid < NG) {
        const float* t = S->tg + tid * 11;
        float4 bx = make_float4(t[0], t[1], t[2], t[3]);
        S->box[tid] = bx;
        S->taa[tid] = (bx.z - bx.x) * (bx.w - bx.y);
        S->bp[tid] = 0x7fffffff;
    }
    __syncthreads();

    // ---- pass 1: matching; per-g max via fmax only (index recovered later) ----
    float qv[NG];
#pragma unroll
    for (int g = 0; g < NG; g++) qv[g] = 0.0f;

#pragma unroll 1
    for (int p = tid; p < NP; p += NTHREADS) {
        float4 pr = __ldg((const float4*)priors + p);
        float pax, pay, pbx, pby, pare;
        prior_derive(pr, pax, pay, pbx, pby, pare);
        float bq = -1.0f;
        int bg = 0;
#pragma unroll
        for (int g = 0; g < NG; g++) {
            float q = qcalc(S->box[g], S->taa[g], pax, pay, pbx, pby, pare);
            if (q > bq) { bq = q; bg = g; }           // strict > : first max over g
            qv[g] = fmaxf(qv[g], q);                  // value-only running max
        }
        S->gp[p] = (unsigned char)bg | ((bq >= 0.5f) ? 0x10 : 0x00);
    }

    // ---- per-gt max value: warp fmax reduce -> block reduce ----
#pragma unroll
    for (int g = 0; g < NG; g++) {
        float q = qv[g];
#pragma unroll
        for (int o = 16; o > 0; o >>= 1)
            q = fmaxf(q, __shfl_down_sync(0xffffffffu, q, o));
        if (lane == 0) S->qmaxw[g * NWARPS + wrp] = q;
    }
    __syncthreads();
    if (tid < NG) {
        float q = S->qmaxw[tid * NWARPS];
        for (int w = 1; w < NWARPS; w++)
            q = fmaxf(q, S->qmaxw[tid * NWARPS + w]);
        S->qmax[tid] = q;
    }
    __syncthreads();

    // ---- exact argmax-index recovery (deterministic recompute) ----
    {
        unsigned mask = 0u;
#pragma unroll
        for (int g = 0; g < NG; g++)
            if (qv[g] == S->qmax[g]) mask |= (1u << g);
        if (mask) {
#pragma unroll 1
            for (int p = tid; p < NP && mask; p += NTHREADS) {
                float4 pr = __ldg((const float4*)priors + p);
                float pax, pay, pbx, pby, pare;
                prior_derive(pr, pax, pay, pbx, pby, pare);
#pragma unroll
                for (int g = 0; g < NG; g++) {
                    if (mask & (1u << g)) {
                        float q = qcalc(S->box[g], S->taa[g], pax, pay, pbx, pby, pare);
                        if (q == S->qmax[g]) {        // bit-identical by construction
                            atomicMin(&S->bp[g], p);  // min p = first occurrence
                            mask &= ~(1u << g);
                        }
                    }
                }
            }
        }
    }
    __syncthreads();
    if (tid == 0) {
#pragma unroll
        for (int j = 0; j < NG; j++) {
            int pp = S->bp[j];
            if (pp < NP) S->gp[pp] = (unsigned char)j | 0x10;  // last wins
        }
    }
    __syncthreads();

    // ---- pass 2: per-prior losses (coalesced staging, no-max LSE) ----
    float ll = 0.0f, lcp = 0.0f;
    int   np = 0;
    float* stg = S->stage + wrp * 672;
    float4* stg4 = (float4*)stg;
    const float* confb = conf_data + (size_t)b * NP * NC;

#pragma unroll 1
    for (int tile = wrp; tile < NTILES; tile += NWARPS) {
        const int p0 = tile * 32;
        const int cnt = (NP - p0 < 32) ? (NP - p0) : 32;
        const int tcnt4 = (cnt * NC) >> 2;
        const float4* cb4 = (const float4*)(confb + (size_t)p0 * NC);
#pragma unroll
        for (int j = 0; j < 6; j++) {
            int idx2 = j * 32 + lane;
            if (idx2 < tcnt4) stg4[idx2] = __ldg(cb4 + idx2);
        }
        __syncwarp();

        const int p = p0 + lane;
        if (p < NP) {
            unsigned gpv = S->gp[p];
            int gi = gpv & 15;
            bool pos = (gpv & 0x10) != 0;
            int conf = pos ? ((int)S->tg[gi * 11 + 10] + 1) : 0;

            const float* row = stg + lane * NC;
            float s = 0.0f;
#pragma unroll
            for (int j = 0; j < NC; j++) s += __expf(row[j]);
            float lca = __logf(s) - row[conf];

            float lc = lca;
            if (pos) {
                lc = 0.0f;
                np++;
                lcp += lca;
                const float* t = S->tg + gi * 11;
                float4 pr = __ldg((const float4*)priors + p);
                float vx = 0.1f * pr.z;
                float vy = 0.1f * pr.w;
                float lts[10];
                lts[0] = ((t[0] + t[2]) * 0.5f - pr.x) / vx;
                lts[1] = ((t[1] + t[3]) * 0.5f - pr.y) / vy;
                lts[2] = logf((t[2] - t[0]) / pr.z) / 0.2f;
                lts[3] = logf((t[3] - t[1]) / pr.w) / 0.2f;
                lts[4] = logf(t[4] / pr.z + 0.1f) / 0.2f;
                lts[5] = logf(t[5] / pr.w + 0.1f) / 0.2f;
                lts[6] = logf(t[6] / pr.z + 0.1f) / 0.2f;
                lts[7] = logf(t[7] / pr.w + 0.1f) / 0.2f;
                lts[8] = (t[8] - pr.x) / vx;
                lts[9] = (t[9] - pr.y) / vy;
                const float* ld = loc_data + ((size_t)b * NP + p) * 10;
#pragma unroll
                for (int j = 0; j < 10; j++) {
                    float d  = __ldg(ld + j) - lts[j];
                    float ad = fabsf(d);
                    ll += (ad < 1.0f) ? (0.5f * d) * d : (ad - 0.5f);
                }
            }
            S->lc[p] = lc;
        }
        __syncwarp();
    }
    __syncthreads();

    // ---- block reduce np / ll / lcp ----
#pragma unroll
    for (int o = 16; o > 0; o >>= 1) {
        ll  += __shfl_down_sync(0xffffffffu, ll, o);
        lcp += __shfl_down_sync(0xffffffffu, lcp, o);
        np  += __shfl_down_sync(0xffffffffu, np, o);
    }
    if (lane == 0) { S->rf[wrp] = ll; S->rf2[wrp] = lcp; S->ri[wrp] = np; }
    __syncthreads();
    if (tid < 32) {
        float ll_t = S->rf[tid], lcp_t = S->rf2[tid];
        int   np_t = S->ri[tid];
#pragma unroll
        for (int o = 16; o > 0; o >>= 1) {
            ll_t  += __shfl_down_sync(0xffffffffu, ll_t, o);
            lcp_t += __shfl_down_sync(0xffffffffu, lcp_t, o);
            np_t  += __shfl_down_sync(0xffffffffu, np_t, o);
        }
        if (tid == 0) { S->rf[0] = ll_t; S->rf2[0] = lcp_t; S->bc[0] = np_t; }
    }
    __syncthreads();
    const int np_tot = S->bc[0];
    const float ll_tot = S->rf[0];
    const float lcp_tot = S->rf2[0];
    int k = 3 * np_tot;
    if (k > NP - 1) k = NP - 1;

    // ---- exact top-k sum via 3-round radix select ----
    float Ssum = 0.0f;
    if (k > 0) {
        unsigned prefix = 0u, pmask = 0u;
        const int shifts[3] = {21, 10, 0};
        const int rbits[3]  = {11, 11, 10};
        int kk = k;
        for (int r = 0; r < 3; r++) {
            for (int i = tid; i < 2048; i += NTHREADS) hist[i] = 0u;
            __syncthreads();
            const unsigned nb = 1u << rbits[r];
#pragma unroll 1
            for (int p = tid; p < 9216; p += NTHREADS) {
                bool valid = p < NP;
                unsigned bb = valid ? __float_as_uint(S->lc[p]) : 0u;
                bool sel = valid && ((bb & pmask) == prefix);
                unsigned bin = sel ? ((bb >> shifts[r]) & (nb - 1u)) : 0xffffffffu;
                unsigned grp = __match_any_sync(0xffffffffu, bin);
                if (sel && lane == (__ffs(grp) - 1))
                    atomicAdd(&hist[bin], (unsigned)__popc(grp));
            }
            __syncthreads();
            unsigned h0 = hist[tid * 2 + 0], h1 = hist[tid * 2 + 1];
            unsigned sloc = h0 + h1;
            unsigned suf = sloc;
#pragma unroll
            for (int o = 1; o < 32; o <<= 1) {
                unsigned v = __shfl_down_sync(0xffffffffu, suf, o);
                if (lane + o < 32) suf += v;
            }
            if (lane == 0) S->gsum[wrp] = suf;
            __syncthreads();
            unsigned above = 0;
            for (int w = wrp + 1; w < NWARPS; w++) above += S->gsum[w];
            unsigned excl1 = above + (suf - sloc);
            unsigned excl0 = excl1 + h1;
            unsigned ukk = (unsigned)kk;
            if (excl1 < ukk && ukk <= excl1 + h1) { S->bc[1] = tid * 2 + 1; S->bc[2] = (int)(ukk - excl1); }
            if (excl0 < ukk && ukk <= excl0 + h0) { S->bc[1] = tid * 2 + 0; S->bc[2] = (int)(ukk - excl0); }
            __syncthreads();
            int chosen = S->bc[1];
            kk = S->bc[2];
            prefix |= ((unsigned)chosen) << shifts[r];
            pmask  |= ((1u << rbits[r]) - 1u) << shifts[r];
            __syncthreads();
        }
        const float tv = __uint_as_float(prefix);
        float sgt = 0.0f;
        int   cgt = 0;
#pragma unroll 1
        for (int p = tid; p < NP; p += NTHREADS) {
            float v = S->lc[p];
            if (__float_as_uint(v) > prefix) { sgt += v; cgt++; }
        }
#pragma unroll
        for (int o = 16; o > 0; o >>= 1) {
            sgt += __shfl_down_sync(0xffffffffu, sgt, o);
            cgt += __shfl_down_sync(0xffffffffu, cgt, o);
        }
        if (lane == 0) { S->rf[wrp] = sgt; S->ri[wrp] = cgt; }
        __syncthreads();
        if (tid == 0) {
            float sgt_t = 0.0f;
            int   cgt_t = 0;
            for (int w = 0; w < NWARPS; w++) { sgt_t += S->rf[w]; cgt_t += S->ri[w]; }
            Ssum = sgt_t + (float)(k - cgt_t) * tv;
        }
    }

    // ---- publish per-batch partials; last CTA finalizes ----
    __shared__ bool slast;
    if (tid == 0) {
        g_bll[b] = ll_tot;
        g_blc[b] = lcp_tot + Ssum;
        g_bnp[b] = np_tot;
        __threadfence();
        unsigned t = atomicAdd(&g_arrive, 1u);
        slast = (t == gridDim.x - 1);
        if (slast) g_arrive = 0u;
    }
    __syncthreads();
    if (slast) {
        float fll = 0.0f, flc = 0.0f;
        int   fnp = 0;
        for (int i = tid; i < (int)gridDim.x; i += NTHREADS) {
            fll += g_bll[i]; flc += g_blc[i]; fnp += g_bnp[i];
        }
#pragma unroll
        for (int o = 16; o > 0; o >>= 1) {
            fll += __shfl_down_sync(0xffffffffu, fll, o);
            flc += __shfl_down_sync(0xffffffffu, flc, o);
            fnp += __shfl_down_sync(0xffffffffu, fnp, o);
        }
        if (lane == 0) { S->rf[wrp] = fll; S->rf2[wrp] = flc; S->ri[wrp] = fnp; }
        __syncthreads();
        if (tid == 0) {
            float tll = 0.0f, tlc = 0.0f;
            int tnp = 0;
            for (int w = 0; w < NWARPS; w++) { tll += S->rf[w]; tlc += S->rf2[w]; tnp += S->ri[w]; }
            float N = (float)tnp;
            out[0] = tll / N;
            out[1] = tlc / N;
        }
    }
}

extern "C" void kernel_launch(void* const* d_in, const int* in_sizes, int n_in,
                              void* d_out, int out_size) {
    const float* loc     = (const float*)d_in[0];
    const float* conf    = (const float*)d_in[1];
    const float* priors  = (const float*)d_in[2];
    const float* targets = (const float*)d_in[3];
    const int B = in_sizes[0] / (NP * 10);

    cudaFuncSetAttribute(mb_main, cudaFuncAttributeMaxDynamicSharedMemorySize,
                         (int)sizeof(Smem));
    mb_main<<<B, NTHREADS, sizeof(Smem)>>>(loc, conf, priors, targets, (float*)d_out);
}